// round 3
// baseline (speedup 1.0000x reference)
#include <cuda_runtime.h>

// ---------------- problem constants ----------------
#define IMG_H 360
#define IMG_W 640
#define N_PTS (IMG_H * IMG_W)      // 230400
#define N_PLANES 1000
#define MIN_PTS 5000

#define CXc 334.081f
#define CYc 169.808f
#define FXc 460.585f
#define FYc 460.268f

#define F_INF __int_as_float(0x7f800000)

// ---------------- device scratch (no allocs allowed) ----------------
static __device__ double g_sX, g_sY, g_sZ, g_sL;
static __device__ int    g_cnt;
static __device__ float  g_max;
static __device__ float4 g_pts[N_PTS];         // nan_cloud, then normalized pts
static __device__ float4 g_plane[N_PLANES];    // (n0,n1,n2,kk)
static __device__ int    g_counts[N_PLANES];
static __device__ float  g_zc[N_PTS];
static __device__ unsigned char g_mask[N_PTS];
static __device__ int    g_icnt;
static __device__ float  g_zmax, g_zmin;
static __device__ double g_below, g_above;
static __device__ float  g_bp[8];              // a,b,c,d, r20,r21,r22, d/c

// ---------------- helpers ----------------
__device__ __forceinline__ unsigned rotl32(unsigned v, int d) {
    return (v << d) | (v >> (32 - d));
}

// JAX threefry2x32, 20 rounds, key schedule per jax._src.prng
__device__ __forceinline__ void threefry2x32(unsigned k0, unsigned k1,
                                             unsigned x0, unsigned x1,
                                             unsigned& o0, unsigned& o1) {
    unsigned ks2 = k0 ^ k1 ^ 0x1BD11BDAu;
#define TF_R(r) { x0 += x1; x1 = rotl32(x1, (r)); x1 ^= x0; }
    x0 += k0;  x1 += k1;
    TF_R(13) TF_R(15) TF_R(26) TF_R(6)
    x0 += k1;  x1 += ks2 + 1u;
    TF_R(17) TF_R(29) TF_R(16) TF_R(24)
    x0 += ks2; x1 += k0 + 2u;
    TF_R(13) TF_R(15) TF_R(26) TF_R(6)
    x0 += k0;  x1 += k1 + 3u;
    TF_R(17) TF_R(29) TF_R(16) TF_R(24)
    x0 += k1;  x1 += ks2 + 4u;
    TF_R(13) TF_R(15) TF_R(26) TF_R(6)
    x0 += ks2; x1 += k0 + 5u;
#undef TF_R
    o0 = x0; o1 = x1;
}

__device__ __forceinline__ float get_thresh(int epoch) {
    float a = (float)(0.025 - 0.001 * (double)epoch);  // matches jnp.float32(py-float)
    return fmaxf(a, 0.005f);
}

// block reductions for blockDim.x == 256 (8 warps)
__device__ __forceinline__ double blockSumD(double v) {
    __shared__ double sh[8];
    int lane = threadIdx.x & 31, w = threadIdx.x >> 5;
    for (int o = 16; o; o >>= 1) v += __shfl_down_sync(0xffffffffu, v, o);
    __syncthreads();
    if (lane == 0) sh[w] = v;
    __syncthreads();
    if (w == 0) {
        v = (lane < 8) ? sh[lane] : 0.0;
        for (int o = 4; o; o >>= 1) v += __shfl_down_sync(0xffffffffu, v, o);
    }
    return v;  // valid in thread 0
}

__device__ __forceinline__ int blockSumI(int v) {
    __shared__ int sh[8];
    int lane = threadIdx.x & 31, w = threadIdx.x >> 5;
    for (int o = 16; o; o >>= 1) v += __shfl_down_sync(0xffffffffu, v, o);
    __syncthreads();
    if (lane == 0) sh[w] = v;
    __syncthreads();
    if (w == 0) {
        v = (lane < 8) ? sh[lane] : 0;
        for (int o = 4; o; o >>= 1) v += __shfl_down_sync(0xffffffffu, v, o);
    }
    return v;
}

__device__ __forceinline__ float blockMaxF(float v) {
    __shared__ float sh[8];
    int lane = threadIdx.x & 31, w = threadIdx.x >> 5;
    for (int o = 16; o; o >>= 1) v = fmaxf(v, __shfl_down_sync(0xffffffffu, v, o));
    __syncthreads();
    if (lane == 0) sh[w] = v;
    __syncthreads();
    if (w == 0) {
        v = (lane < 8) ? sh[lane] : -F_INF;
        for (int o = 4; o; o >>= 1) v = fmaxf(v, __shfl_down_sync(0xffffffffu, v, o));
    }
    return v;
}

__device__ __forceinline__ float blockMinF(float v) {
    __shared__ float sh[8];
    int lane = threadIdx.x & 31, w = threadIdx.x >> 5;
    for (int o = 16; o; o >>= 1) v = fminf(v, __shfl_down_sync(0xffffffffu, v, o));
    __syncthreads();
    if (lane == 0) sh[w] = v;
    __syncthreads();
    if (w == 0) {
        v = (lane < 8) ? sh[lane] : F_INF;
        for (int o = 4; o; o >>= 1) v = fminf(v, __shfl_down_sync(0xffffffffu, v, o));
    }
    return v;
}

__device__ __forceinline__ void atomicMaxF(float* addr, float v) {
    if (!(v == v)) return;
    int old = __float_as_int(*addr);
    while (__int_as_float(old) < v) {
        int assumed = old;
        old = atomicCAS((int*)addr, assumed, __float_as_int(v));
        if (old == assumed) break;
    }
}

__device__ __forceinline__ void atomicMinF(float* addr, float v) {
    if (!(v == v)) return;
    int old = __float_as_int(*addr);
    while (__int_as_float(old) > v) {
        int assumed = old;
        old = atomicCAS((int*)addr, assumed, __float_as_int(v));
        if (old == assumed) break;
    }
}

// ---------------- kernels ----------------
__global__ void k_init() {
    int t = blockIdx.x * blockDim.x + threadIdx.x;
    if (t < N_PLANES) g_counts[t] = 0;
    if (t == 0) {
        g_sX = 0.0; g_sY = 0.0; g_sZ = 0.0; g_sL = 0.0;
        g_cnt = 0; g_icnt = 0;
        g_max  = -F_INF;
        g_zmax = -F_INF;
        g_zmin =  F_INF;
        g_below = 0.0; g_above = 0.0;
    }
}

// Stage A: point clouds, masked loss sums, nan_cloud + max
__global__ void k_pcd(const float* __restrict__ fake, const float* __restrict__ real) {
    int i = blockIdx.x * blockDim.x + threadIdx.x;  // exactly N_PTS threads
    int r = i / IMG_W, c = i % IMG_W;
    float dr = real[i], df = fake[i];
    bool vr = (dr > 0.f) && (dr < 65535.f);
    bool vf = (df > 0.f) && (df < 65535.f);
    float cf = (float)c, rf = (float)r;

    float zr = dr / 1000.f, zf = df / 1000.f;
    float xr = zr * (cf - CXc) / FXc, yr = zr * (rf - CYc) / FYc;
    float xf = zf * (cf - CXc) / FXc, yf = zf * (rf - CYc) / FYc;
    xr *= 1000.f; yr *= 1000.f; zr *= 1000.f;
    xf *= 1000.f; yf *= 1000.f; zf *= 1000.f;
    if (xr == 0.f) xr = 1e-7f;  if (yr == 0.f) yr = 1e-7f;  if (zr == 0.f) zr = 1e-7f;
    if (xf == 0.f) xf = 1e-7f;  if (yf == 0.f) yf = 1e-7f;  if (zf == 0.f) zf = 1e-7f;

    double dx = 0.0, dy = 0.0, dz = 0.0, dl = 0.0;
    int mm = 0;
    if (vr && vf) {
        float ex = xr - xf, ey = yr - yf, ez = zr - zf;
        dx = (double)(ex * ex); dy = (double)(ey * ey); dz = (double)(ez * ez);
        float d0 = logf(fabsf(zr)) - logf(fabsf(zf));
        dl = (double)(d0 * d0);
        mm = 1;
    }
    float4 nc = vf ? make_float4(xf, yf, zf, 0.f) : make_float4(0.f, 0.f, 0.f, 0.f);
    g_pts[i] = nc;
    float mxv = fmaxf(nc.x, fmaxf(nc.y, nc.z));

    double s;
    s = blockSumD(dx); if (threadIdx.x == 0) atomicAdd(&g_sX, s);
    s = blockSumD(dy); if (threadIdx.x == 0) atomicAdd(&g_sY, s);
    s = blockSumD(dz); if (threadIdx.x == 0) atomicAdd(&g_sZ, s);
    s = blockSumD(dl); if (threadIdx.x == 0) atomicAdd(&g_sL, s);
    int cs = blockSumI(mm); if (threadIdx.x == 0) atomicAdd(&g_cnt, cs);
    float bm = blockMaxF(mxv); if (threadIdx.x == 0) atomicMaxF(&g_max, bm);
}

__global__ void k_norm() {
    int i = blockIdx.x * blockDim.x + threadIdx.x;
    float m = g_max;
    float4 p = g_pts[i];
    p.x = p.x / m; p.y = p.y / m; p.z = p.z / m;
    g_pts[i] = p;
}

// Stage B: 1000 RANSAC planes from JAX-exact threefry randint
__global__ void k_planes() {
    int j = blockIdx.x * blockDim.x + threadIdx.x;
    if (j >= N_PLANES) return;
    float3 p[3];
#pragma unroll
    for (int k = 0; k < 3; k++) {
        unsigned f = (unsigned)(j * 3 + k);
        unsigned o0, o1;
        threefry2x32(0u, 42u, f, 3000u + f, o0, o1);
        // span = 230400 > 2^16 => JAX multiplier wraps to 0 => idx = lower_bits % span
        unsigned idx = o1 % (unsigned)N_PTS;
        float4 q = g_pts[idx];
        p[k] = make_float3(q.x, q.y, q.z);
    }
    float ax = p[1].x - p[0].x, ay = p[1].y - p[0].y, az = p[1].z - p[0].z;
    float bx = p[2].x - p[0].x, by = p[2].y - p[0].y, bz = p[2].z - p[0].z;
    float nx = ay * bz - az * by;
    float ny = az * bx - ax * bz;
    float nz = ax * by - ay * bx;
    float nn = sqrtf(nx * nx + ny * ny + nz * nz);
    nx /= nn; ny /= nn; nz /= nn;
    float kk = -(nx * p[1].x + ny * p[1].y + nz * p[1].z);
    g_plane[j] = make_float4(nx, ny, nz, kk);
}

// Stage C: inlier counts. SMEM point tile, 2 planes/thread in registers.
#define CT_TILE 2048
__global__ void k_counts(const int* __restrict__ ep) {
    __shared__ float4 sp[CT_TILE];
    float th = get_thresh(*ep);

    int j0 = blockIdx.y * 512 + threadIdx.x;
    int j1 = j0 + 256;
    float4 plA = g_plane[j0 < N_PLANES ? j0 : 0];
    float4 plB = g_plane[j1 < N_PLANES ? j1 : 0];

    int base = blockIdx.x * CT_TILE;
    for (int t = threadIdx.x; t < CT_TILE; t += 256) {
        int ii = base + t;
        sp[t] = (ii < N_PTS) ? g_pts[ii]
                             : make_float4(__int_as_float(0x7fc00000), 0.f, 0.f, 0.f);
    }
    __syncthreads();

    int c0 = 0, c1 = 0;
#pragma unroll 8
    for (int t = 0; t < CT_TILE; t++) {
        float4 p = sp[t];
        float dA = fmaf(p.x, plA.x, fmaf(p.y, plA.y, fmaf(p.z, plA.z, plA.w)));
        float dB = fmaf(p.x, plB.x, fmaf(p.y, plB.y, fmaf(p.z, plB.z, plB.w)));
        c0 += (fabsf(dA) <= th);
        c1 += (fabsf(dB) <= th);
    }
    if (j0 < N_PLANES) atomicAdd(&g_counts[j0], c0);
    if (j1 < N_PLANES) atomicAdd(&g_counts[j1], c1);
}

// Stage D1: argmax (first occurrence) + best-plane rotation params
__global__ void k_best() {
    __shared__ int sVal[1024];
    __shared__ int sIdx[1024];
    int t = threadIdx.x;
    int val = -2, idx = t;
    if (t < N_PLANES) {
        int cc = g_counts[t];
        val = (cc > MIN_PTS) ? cc : -1;
    }
    sVal[t] = val; sIdx[t] = idx;
    __syncthreads();
    for (int s = 512; s > 0; s >>= 1) {
        if (t < s) {
            if (sVal[t + s] > sVal[t] ||
                (sVal[t + s] == sVal[t] && sIdx[t + s] < sIdx[t])) {
                sVal[t] = sVal[t + s];
                sIdx[t] = sIdx[t + s];
            }
        }
        __syncthreads();
    }
    if (t == 0) {
        int best = sIdx[0];
        float4 pl = g_plane[best];
        float a = pl.x, b = pl.y, c = pl.z, d = pl.w;
        float n2 = a * a + b * b + c * c;
        float cos_t = c / sqrtf(n2);
        float sin_t = sqrtf((a * a + b * b) / n2);
        float sab = sqrtf(a * a + b * b);
        float u1 = b / sab, u2 = -a / sab;
        g_bp[0] = a; g_bp[1] = b; g_bp[2] = c; g_bp[3] = d;
        g_bp[4] = -u2 * sin_t;   // R[2,0]
        g_bp[5] =  u1 * sin_t;   // R[2,1]
        g_bp[6] =  cos_t;        // R[2,2]
        g_bp[7] =  d / c;        // trans z
    }
}

// Stage D2: zc + inlier mask + icnt/zmax/zmin
__global__ void k_zc(const int* __restrict__ ep) {
    float th = get_thresh(*ep);
    int i = blockIdx.x * blockDim.x + threadIdx.x;
    float4 p = g_pts[i];
    float dist = fmaf(p.x, g_bp[0], fmaf(p.y, g_bp[1], fmaf(p.z, g_bp[2], g_bp[3])));
    bool inl = fabsf(dist) <= th;
    float zc = p.x * g_bp[4] + p.y * g_bp[5] + (p.z + g_bp[7]) * g_bp[6];
    g_zc[i] = zc;
    g_mask[i] = inl ? 1 : 0;

    int ic = blockSumI(inl ? 1 : 0);
    float zmx = blockMaxF(inl ? zc : -F_INF);
    float zmn = blockMinF(inl ? zc :  F_INF);
    if (threadIdx.x == 0) {
        atomicAdd(&g_icnt, ic);
        atomicMaxF(&g_zmax, zmx);
        atomicMinF(&g_zmin, zmn);
    }
}

// Stage D3: sums of |zc - zmax| and |zc - zmin| over inliers
__global__ void k_tails() {
    int i = blockIdx.x * blockDim.x + threadIdx.x;
    bool inl = g_mask[i] != 0;
    float zc = g_zc[i];
    double db = inl ? (double)fabsf(zc - g_zmax) : 0.0;
    double da = inl ? (double)fabsf(zc - g_zmin) : 0.0;
    double s;
    s = blockSumD(db); if (threadIdx.x == 0) atomicAdd(&g_below, s);
    s = blockSumD(da); if (threadIdx.x == 0) atomicAdd(&g_above, s);
}

__global__ void k_fin(float* __restrict__ out, int n) {
    float cntf = (float)(g_cnt > 1 ? g_cnt : 1);
    float lX = sqrtf((float)g_sX / cntf);
    float lY = sqrtf((float)g_sY / cntf);
    float lZ = sqrtf((float)g_sZ / cntf);
    float rl = 10000.f * sqrtf((float)g_sL / cntf);
    float l17 = rl * fabsf(10.f * (3.f - expf(lX) - expf(lY) - expf(lZ)));
    float icf = (float)(g_icnt > 1 ? g_icnt : 1);
    float below = (float)g_below / icf;
    float above = (float)g_above / icf;
    if (above == 0.f) above = 1e-7f;
    float pmd = 1000.f * (above + below);
    float curv = l17 + pmd;
    float vals[7] = { rl, lX, lY, lZ, pmd, l17, curv };
    for (int i = 0; i < n; i++) out[i] = (i < 7) ? vals[i] : 0.f;
}

// ---------------- launch ----------------
extern "C" void kernel_launch(void* const* d_in, const int* in_sizes, int n_in,
                              void* d_out, int out_size) {
    const float* fake = (const float*)d_in[0];
    const float* real = (const float*)d_in[1];
    const int*   ep   = (const int*)d_in[2];
    float* out = (float*)d_out;

    const int NB = N_PTS / 256;  // 900, exact

    k_init<<<1, 1024>>>();
    k_pcd<<<NB, 256>>>(fake, real);
    k_norm<<<NB, 256>>>();
    k_planes<<<4, 256>>>();
    dim3 cg((N_PTS + CT_TILE - 1) / CT_TILE, 2);
    k_counts<<<cg, 256>>>(ep);
    k_best<<<1, 1024>>>();
    k_zc<<<NB, 256>>>(ep);
    k_tails<<<NB, 256>>>();
    k_fin<<<1, 1>>>(out, out_size);
}

// round 4
// speedup vs baseline: 1.4327x; 1.4327x over previous
#include <cuda_runtime.h>

// ---------------- problem constants ----------------
#define IMG_H 360
#define IMG_W 640
#define N_PTS (IMG_H * IMG_W)      // 230400
#define N_PLANES 1000
#define MIN_PTS 5000

#define CXc 334.081f
#define CYc 169.808f
#define FXc 460.585f
#define FYc 460.268f

#define F_INF __int_as_float(0x7f800000)

// ---------------- device scratch (no allocs allowed) ----------------
static __device__ double g_sX, g_sY, g_sZ, g_sL;
static __device__ int    g_cnt;
static __device__ float  g_max;
static __device__ float4 g_pts[N_PTS];         // UNNORMALIZED nan_cloud
static __device__ float4 g_plane[N_PLANES];    // (n0,n1,n2,kk) from normalized pts
static __device__ int    g_counts[N_PLANES];
static __device__ int    g_icnt;
static __device__ float  g_zmax, g_zmin;
static __device__ double g_sZC;                // sum of inlier zc
static __device__ float  g_bp[8];              // a,b,c,d, r20,r21,r22, d/c
static __device__ int    g_tick_counts, g_tick_zc;

// ---------------- f32x2 packed math (Blackwell FFMA2) ----------------
__device__ __forceinline__ unsigned long long pack2(float a, float b) {
    unsigned long long r;
    asm("mov.b64 %0, {%1, %2};" : "=l"(r) : "f"(a), "f"(b));
    return r;
}
__device__ __forceinline__ unsigned long long fma2(unsigned long long a,
                                                   unsigned long long b,
                                                   unsigned long long c) {
    unsigned long long d;
    asm("fma.rn.f32x2 %0, %1, %2, %3;" : "=l"(d) : "l"(a), "l"(b), "l"(c));
    return d;
}
__device__ __forceinline__ void unpack2(unsigned long long v, float& lo, float& hi) {
    asm("mov.b64 {%0, %1}, %2;" : "=f"(lo), "=f"(hi) : "l"(v));
}

// ---------------- helpers ----------------
__device__ __forceinline__ unsigned rotl32(unsigned v, int d) {
    return (v << d) | (v >> (32 - d));
}

// JAX threefry2x32, 20 rounds
__device__ __forceinline__ void threefry2x32(unsigned k0, unsigned k1,
                                             unsigned x0, unsigned x1,
                                             unsigned& o0, unsigned& o1) {
    unsigned ks2 = k0 ^ k1 ^ 0x1BD11BDAu;
#define TF_R(r) { x0 += x1; x1 = rotl32(x1, (r)); x1 ^= x0; }
    x0 += k0;  x1 += k1;
    TF_R(13) TF_R(15) TF_R(26) TF_R(6)
    x0 += k1;  x1 += ks2 + 1u;
    TF_R(17) TF_R(29) TF_R(16) TF_R(24)
    x0 += ks2; x1 += k0 + 2u;
    TF_R(13) TF_R(15) TF_R(26) TF_R(6)
    x0 += k0;  x1 += k1 + 3u;
    TF_R(17) TF_R(29) TF_R(16) TF_R(24)
    x0 += k1;  x1 += ks2 + 4u;
    TF_R(13) TF_R(15) TF_R(26) TF_R(6)
    x0 += ks2; x1 += k0 + 5u;
#undef TF_R
    o0 = x0; o1 = x1;
}

__device__ __forceinline__ float get_thresh(int epoch) {
    float a = (float)(0.025 - 0.001 * (double)epoch);
    return fmaxf(a, 0.005f);
}

// block reductions for blockDim.x == 256 (8 warps)
__device__ __forceinline__ double blockSumD(double v) {
    __shared__ double sh[8];
    int lane = threadIdx.x & 31, w = threadIdx.x >> 5;
    for (int o = 16; o; o >>= 1) v += __shfl_down_sync(0xffffffffu, v, o);
    __syncthreads();
    if (lane == 0) sh[w] = v;
    __syncthreads();
    if (w == 0) {
        v = (lane < 8) ? sh[lane] : 0.0;
        for (int o = 4; o; o >>= 1) v += __shfl_down_sync(0xffffffffu, v, o);
    }
    return v;
}
__device__ __forceinline__ int blockSumI(int v) {
    __shared__ int sh[8];
    int lane = threadIdx.x & 31, w = threadIdx.x >> 5;
    for (int o = 16; o; o >>= 1) v += __shfl_down_sync(0xffffffffu, v, o);
    __syncthreads();
    if (lane == 0) sh[w] = v;
    __syncthreads();
    if (w == 0) {
        v = (lane < 8) ? sh[lane] : 0;
        for (int o = 4; o; o >>= 1) v += __shfl_down_sync(0xffffffffu, v, o);
    }
    return v;
}
__device__ __forceinline__ float blockMaxF(float v) {
    __shared__ float sh[8];
    int lane = threadIdx.x & 31, w = threadIdx.x >> 5;
    for (int o = 16; o; o >>= 1) v = fmaxf(v, __shfl_down_sync(0xffffffffu, v, o));
    __syncthreads();
    if (lane == 0) sh[w] = v;
    __syncthreads();
    if (w == 0) {
        v = (lane < 8) ? sh[lane] : -F_INF;
        for (int o = 4; o; o >>= 1) v = fmaxf(v, __shfl_down_sync(0xffffffffu, v, o));
    }
    return v;
}
__device__ __forceinline__ float blockMinF(float v) {
    __shared__ float sh[8];
    int lane = threadIdx.x & 31, w = threadIdx.x >> 5;
    for (int o = 16; o; o >>= 1) v = fminf(v, __shfl_down_sync(0xffffffffu, v, o));
    __syncthreads();
    if (lane == 0) sh[w] = v;
    __syncthreads();
    if (w == 0) {
        v = (lane < 8) ? sh[lane] : F_INF;
        for (int o = 4; o; o >>= 1) v = fminf(v, __shfl_down_sync(0xffffffffu, v, o));
    }
    return v;
}

__device__ __forceinline__ void atomicMaxF(float* addr, float v) {
    if (!(v == v)) return;
    int old = __float_as_int(*addr);
    while (__int_as_float(old) < v) {
        int assumed = old;
        old = atomicCAS((int*)addr, assumed, __float_as_int(v));
        if (old == assumed) break;
    }
}
__device__ __forceinline__ void atomicMinF(float* addr, float v) {
    if (!(v == v)) return;
    int old = __float_as_int(*addr);
    while (__int_as_float(old) > v) {
        int assumed = old;
        old = atomicCAS((int*)addr, assumed, __float_as_int(v));
        if (old == assumed) break;
    }
}

// ---------------- kernels ----------------
__global__ void k_init() {
    int t = blockIdx.x * blockDim.x + threadIdx.x;
    if (t < N_PLANES) g_counts[t] = 0;
    if (t == 0) {
        g_sX = 0.0; g_sY = 0.0; g_sZ = 0.0; g_sL = 0.0;
        g_cnt = 0; g_icnt = 0;
        g_max  = -F_INF;
        g_zmax = -F_INF;
        g_zmin =  F_INF;
        g_sZC  = 0.0;
        g_tick_counts = 0;
        g_tick_zc = 0;
    }
}

// Stage A: point clouds, masked loss sums, nan_cloud + global max
__global__ void k_pcd(const float* __restrict__ fake, const float* __restrict__ real) {
    int i = blockIdx.x * blockDim.x + threadIdx.x;  // exactly N_PTS threads
    int r = i / IMG_W, c = i % IMG_W;
    float dr = real[i], df = fake[i];
    bool vr = (dr > 0.f) && (dr < 65535.f);
    bool vf = (df > 0.f) && (df < 65535.f);
    float cf = (float)c, rf = (float)r;

    float zr = dr / 1000.f, zf = df / 1000.f;
    float xr = zr * (cf - CXc) / FXc, yr = zr * (rf - CYc) / FYc;
    float xf = zf * (cf - CXc) / FXc, yf = zf * (rf - CYc) / FYc;
    xr *= 1000.f; yr *= 1000.f; zr *= 1000.f;
    xf *= 1000.f; yf *= 1000.f; zf *= 1000.f;
    if (xr == 0.f) xr = 1e-7f;  if (yr == 0.f) yr = 1e-7f;  if (zr == 0.f) zr = 1e-7f;
    if (xf == 0.f) xf = 1e-7f;  if (yf == 0.f) yf = 1e-7f;  if (zf == 0.f) zf = 1e-7f;

    double dx = 0.0, dy = 0.0, dz = 0.0, dl = 0.0;
    int mm = 0;
    if (vr && vf) {
        float ex = xr - xf, ey = yr - yf, ez = zr - zf;
        dx = (double)(ex * ex); dy = (double)(ey * ey); dz = (double)(ez * ez);
        float d0 = logf(fabsf(zr)) - logf(fabsf(zf));
        dl = (double)(d0 * d0);
        mm = 1;
    }
    float4 nc = vf ? make_float4(xf, yf, zf, 0.f) : make_float4(0.f, 0.f, 0.f, 0.f);
    g_pts[i] = nc;
    float mxv = fmaxf(nc.x, fmaxf(nc.y, nc.z));

    double s;
    s = blockSumD(dx); if (threadIdx.x == 0) atomicAdd(&g_sX, s);
    s = blockSumD(dy); if (threadIdx.x == 0) atomicAdd(&g_sY, s);
    s = blockSumD(dz); if (threadIdx.x == 0) atomicAdd(&g_sZ, s);
    s = blockSumD(dl); if (threadIdx.x == 0) atomicAdd(&g_sL, s);
    int cs = blockSumI(mm); if (threadIdx.x == 0) atomicAdd(&g_cnt, cs);
    float bm = blockMaxF(mxv); if (threadIdx.x == 0) atomicMaxF(&g_max, bm);
}

// Stage B: 1000 RANSAC planes from JAX-exact threefry randint (normalized pts)
__global__ void k_planes() {
    int j = blockIdx.x * blockDim.x + threadIdx.x;
    if (j >= N_PLANES) return;
    float m = g_max;
    float3 p[3];
#pragma unroll
    for (int k = 0; k < 3; k++) {
        unsigned f = (unsigned)(j * 3 + k);
        unsigned o0, o1;
        threefry2x32(0u, 42u, f, 3000u + f, o0, o1);
        // span = 230400 > 2^16 => JAX multiplier wraps to 0 => idx = lower_bits % span
        unsigned idx = o1 % (unsigned)N_PTS;
        float4 q = g_pts[idx];
        p[k] = make_float3(q.x / m, q.y / m, q.z / m);   // same division as reference
    }
    float ax = p[1].x - p[0].x, ay = p[1].y - p[0].y, az = p[1].z - p[0].z;
    float bx = p[2].x - p[0].x, by = p[2].y - p[0].y, bz = p[2].z - p[0].z;
    float nx = ay * bz - az * by;
    float ny = az * bx - ax * bz;
    float nz = ax * by - ay * bx;
    float nn = sqrtf(nx * nx + ny * ny + nz * nz);
    nx /= nn; ny /= nn; nz /= nn;
    float kk = -(nx * p[1].x + ny * p[1].y + nz * p[1].z);
    g_plane[j] = make_float4(nx, ny, nz, kk);
}

// Stage C: inlier counts. 512-pt tile (packed point-pairs), 4 planes/thread,
// FFMA2 packed math. Last block computes argmax + rotation params.
#define CT 512
#define CB (N_PTS / CT)   // 450, exact
__global__ void __launch_bounds__(256) k_counts(const int* __restrict__ ep) {
    __shared__ unsigned long long sx[256], sy[256], sz[256];
    __shared__ int s_last;
    __shared__ int sv[256], si[256];

    float th = get_thresh(*ep);
    float m = g_max;
    int t = threadIdx.x;

    // planes (broadcast into both halves)
    unsigned long long A[4], B4[4], C4[4], K4[4];
    int cnt[4] = {0, 0, 0, 0};
#pragma unroll
    for (int p = 0; p < 4; p++) {
        int j = t + p * 256;
        float4 pl = g_plane[j < N_PLANES ? j : 0];
        A[p]  = pack2(pl.x, pl.x);
        B4[p] = pack2(pl.y, pl.y);
        C4[p] = pack2(pl.z, pl.z);
        K4[p] = pack2(pl.w, pl.w);
    }

    // tile load: point pairs, normalized exactly like reference (f32 divide)
    int base = blockIdx.x * CT;
    {
        float4 q0 = g_pts[base + 2 * t];
        float4 q1 = g_pts[base + 2 * t + 1];
        sx[t] = pack2(q0.x / m, q1.x / m);
        sy[t] = pack2(q0.y / m, q1.y / m);
        sz[t] = pack2(q0.z / m, q1.z / m);
    }
    __syncthreads();

#pragma unroll 4
    for (int i = 0; i < 256; i++) {
        unsigned long long x2 = sx[i], y2 = sy[i], z2 = sz[i];
#pragma unroll
        for (int p = 0; p < 4; p++) {
            unsigned long long d2 = fma2(x2, A[p], fma2(y2, B4[p], fma2(z2, C4[p], K4[p])));
            float d0, d1; unpack2(d2, d0, d1);
            cnt[p] += (fabsf(d0) <= th);
            cnt[p] += (fabsf(d1) <= th);
        }
    }
#pragma unroll
    for (int p = 0; p < 4; p++) {
        int j = t + p * 256;
        if (j < N_PLANES) atomicAdd(&g_counts[j], cnt[p]);
    }

    // ---- last-block tail: argmax (first max) + best-plane rotation ----
    __threadfence();
    if (t == 0) {
        int old = atomicAdd(&g_tick_counts, 1);
        s_last = (old == (int)gridDim.x - 1);
    }
    __syncthreads();
    if (!s_last) return;

    int bv = -2, bi = 0;
    for (int j = t; j < N_PLANES; j += 256) {
        int cc = g_counts[j];
        int v = (cc > MIN_PTS) ? cc : -1;
        if (v > bv) { bv = v; bi = j; }   // ascending j => first max kept
    }
    sv[t] = bv; si[t] = bi;
    __syncthreads();
    for (int s = 128; s > 0; s >>= 1) {
        if (t < s) {
            if (sv[t + s] > sv[t] || (sv[t + s] == sv[t] && si[t + s] < si[t])) {
                sv[t] = sv[t + s]; si[t] = si[t + s];
            }
        }
        __syncthreads();
    }
    if (t == 0) {
        int best = si[0];
        float4 pl = g_plane[best];
        float a = pl.x, b = pl.y, c = pl.z, d = pl.w;
        float n2 = a * a + b * b + c * c;
        float cos_t = c / sqrtf(n2);
        float sin_t = sqrtf((a * a + b * b) / n2);
        float sab = sqrtf(a * a + b * b);
        float u1 = b / sab, u2 = -a / sab;
        g_bp[0] = a; g_bp[1] = b; g_bp[2] = c; g_bp[3] = d;
        g_bp[4] = -u2 * sin_t;   // R[2,0]
        g_bp[5] =  u1 * sin_t;   // R[2,1]
        g_bp[6] =  cos_t;        // R[2,2]
        g_bp[7] =  d / c;        // trans z
    }
}

// Stage D: single pass: inlier mask + icnt/zmax/zmin/sum(zc); last block finalizes.
// Uses identity: sum|zc-zmax| = icnt*zmax - S, sum|zc-zmin| = S - icnt*zmin.
__global__ void k_zc(const int* __restrict__ ep, float* __restrict__ out, int n) {
    __shared__ int s_last;
    float th = get_thresh(*ep);
    float m = g_max;
    int i = blockIdx.x * blockDim.x + threadIdx.x;
    float4 q = g_pts[i];
    float x = q.x / m, y = q.y / m, z = q.z / m;
    float dist = fmaf(x, g_bp[0], fmaf(y, g_bp[1], fmaf(z, g_bp[2], g_bp[3])));
    bool inl = fabsf(dist) <= th;
    float zc = x * g_bp[4] + y * g_bp[5] + (z + g_bp[7]) * g_bp[6];

    int    ic  = blockSumI(inl ? 1 : 0);
    float  zmx = blockMaxF(inl ? zc : -F_INF);
    float  zmn = blockMinF(inl ? zc :  F_INF);
    double s   = blockSumD(inl ? (double)zc : 0.0);
    if (threadIdx.x == 0) {
        atomicAdd(&g_icnt, ic);
        atomicMaxF(&g_zmax, zmx);
        atomicMinF(&g_zmin, zmn);
        atomicAdd(&g_sZC, s);
    }

    __threadfence();
    if (threadIdx.x == 0) {
        int old = atomicAdd(&g_tick_zc, 1);
        s_last = (old == (int)gridDim.x - 1);
    }
    __syncthreads();
    if (!(s_last && threadIdx.x == 0)) return;

    // ---- finalize ----
    float cntf = (float)(g_cnt > 1 ? g_cnt : 1);
    float lX = sqrtf((float)g_sX / cntf);
    float lY = sqrtf((float)g_sY / cntf);
    float lZ = sqrtf((float)g_sZ / cntf);
    float rl = 10000.f * sqrtf((float)g_sL / cntf);
    float l17 = rl * fabsf(10.f * (3.f - expf(lX) - expf(lY) - expf(lZ)));

    int icr = g_icnt;
    float below, above;
    if (icr <= 0) {
        below = 0.f; above = 0.f;
    } else {
        float meanz = (float)(g_sZC / (double)icr);
        below = g_zmax - meanz;
        above = meanz - g_zmin;
    }
    if (above == 0.f) above = 1e-7f;
    float pmd = 1000.f * (above + below);
    float curv = l17 + pmd;
    float vals[7] = { rl, lX, lY, lZ, pmd, l17, curv };
    for (int k = 0; k < n; k++) out[k] = (k < 7) ? vals[k] : 0.f;
}

// ---------------- launch ----------------
extern "C" void kernel_launch(void* const* d_in, const int* in_sizes, int n_in,
                              void* d_out, int out_size) {
    const float* fake = (const float*)d_in[0];
    const float* real = (const float*)d_in[1];
    const int*   ep   = (const int*)d_in[2];
    float* out = (float*)d_out;

    const int NB = N_PTS / 256;  // 900, exact

    k_init<<<4, 256>>>();
    k_pcd<<<NB, 256>>>(fake, real);
    k_planes<<<8, 128>>>();
    k_counts<<<CB, 256>>>(ep);
    k_zc<<<NB, 256>>>(ep, out, out_size);
}

// round 5
// speedup vs baseline: 1.4339x; 1.0008x over previous
#include <cuda_runtime.h>

// ---------------- problem constants ----------------
#define IMG_H 360
#define IMG_W 640
#define N_PTS (IMG_H * IMG_W)      // 230400
#define N_PLANES 1000
#define MIN_PTS 5000

#define CXc 334.081f
#define CYc 169.808f
#define FXc 460.585f
#define FYc 460.268f

#define F_INF __int_as_float(0x7f800000)
#define NEG_FLT_MAX (-3.402823466e38f)
#define POS_FLT_MAX ( 3.402823466e38f)

// ---------------- device scratch (no allocs; self-cleaning per call) ----------------
static __device__ double g_sX = 0.0, g_sY = 0.0, g_sZ = 0.0, g_sL = 0.0;
static __device__ int    g_cnt = 0;
static __device__ float  g_max = NEG_FLT_MAX;
static __device__ float4 g_pts[N_PTS];         // UNNORMALIZED nan_cloud
static __device__ float4 g_plane[N_PLANES];    // (n0,n1,n2,kk) from normalized pts
static __device__ int    g_counts[N_PLANES];   // zero-init, reset by k_counts tail
static __device__ int    g_icnt = 0;
static __device__ float  g_zmax = NEG_FLT_MAX, g_zmin = POS_FLT_MAX;
static __device__ double g_sZC = 0.0;          // sum of inlier zc
static __device__ float  g_bp[8];              // a,b,c,d, r20,r21,r22, d/c
static __device__ int    g_tick_counts = 0, g_tick_zc = 0;

// ---------------- f32x2 packed math (Blackwell FFMA2) ----------------
__device__ __forceinline__ unsigned long long pack2(float a, float b) {
    unsigned long long r;
    asm("mov.b64 %0, {%1, %2};" : "=l"(r) : "f"(a), "f"(b));
    return r;
}
__device__ __forceinline__ unsigned long long fma2(unsigned long long a,
                                                   unsigned long long b,
                                                   unsigned long long c) {
    unsigned long long d;
    asm("fma.rn.f32x2 %0, %1, %2, %3;" : "=l"(d) : "l"(a), "l"(b), "l"(c));
    return d;
}
__device__ __forceinline__ void unpack2(unsigned long long v, float& lo, float& hi) {
    asm("mov.b64 {%0, %1}, %2;" : "=f"(lo), "=f"(hi) : "l"(v));
}

// ---------------- helpers ----------------
__device__ __forceinline__ unsigned rotl32(unsigned v, int d) {
    return (v << d) | (v >> (32 - d));
}

// JAX threefry2x32, 20 rounds
__device__ __forceinline__ void threefry2x32(unsigned k0, unsigned k1,
                                             unsigned x0, unsigned x1,
                                             unsigned& o0, unsigned& o1) {
    unsigned ks2 = k0 ^ k1 ^ 0x1BD11BDAu;
#define TF_R(r) { x0 += x1; x1 = rotl32(x1, (r)); x1 ^= x0; }
    x0 += k0;  x1 += k1;
    TF_R(13) TF_R(15) TF_R(26) TF_R(6)
    x0 += k1;  x1 += ks2 + 1u;
    TF_R(17) TF_R(29) TF_R(16) TF_R(24)
    x0 += ks2; x1 += k0 + 2u;
    TF_R(13) TF_R(15) TF_R(26) TF_R(6)
    x0 += k0;  x1 += k1 + 3u;
    TF_R(17) TF_R(29) TF_R(16) TF_R(24)
    x0 += k1;  x1 += ks2 + 4u;
    TF_R(13) TF_R(15) TF_R(26) TF_R(6)
    x0 += ks2; x1 += k0 + 5u;
#undef TF_R
    o0 = x0; o1 = x1;
}

__device__ __forceinline__ float get_thresh(int epoch) {
    float a = (float)(0.025 - 0.001 * (double)epoch);
    return fmaxf(a, 0.005f);
}

// block reductions for blockDim.x == 256 (8 warps)
__device__ __forceinline__ double blockSumD(double v) {
    __shared__ double sh[8];
    int lane = threadIdx.x & 31, w = threadIdx.x >> 5;
    for (int o = 16; o; o >>= 1) v += __shfl_down_sync(0xffffffffu, v, o);
    __syncthreads();
    if (lane == 0) sh[w] = v;
    __syncthreads();
    if (w == 0) {
        v = (lane < 8) ? sh[lane] : 0.0;
        for (int o = 4; o; o >>= 1) v += __shfl_down_sync(0xffffffffu, v, o);
    }
    return v;
}
__device__ __forceinline__ int blockSumI(int v) {
    __shared__ int sh[8];
    int lane = threadIdx.x & 31, w = threadIdx.x >> 5;
    for (int o = 16; o; o >>= 1) v += __shfl_down_sync(0xffffffffu, v, o);
    __syncthreads();
    if (lane == 0) sh[w] = v;
    __syncthreads();
    if (w == 0) {
        v = (lane < 8) ? sh[lane] : 0;
        for (int o = 4; o; o >>= 1) v += __shfl_down_sync(0xffffffffu, v, o);
    }
    return v;
}
__device__ __forceinline__ float blockMaxF(float v) {
    __shared__ float sh[8];
    int lane = threadIdx.x & 31, w = threadIdx.x >> 5;
    for (int o = 16; o; o >>= 1) v = fmaxf(v, __shfl_down_sync(0xffffffffu, v, o));
    __syncthreads();
    if (lane == 0) sh[w] = v;
    __syncthreads();
    if (w == 0) {
        v = (lane < 8) ? sh[lane] : -F_INF;
        for (int o = 4; o; o >>= 1) v = fmaxf(v, __shfl_down_sync(0xffffffffu, v, o));
    }
    return v;
}
__device__ __forceinline__ float blockMinF(float v) {
    __shared__ float sh[8];
    int lane = threadIdx.x & 31, w = threadIdx.x >> 5;
    for (int o = 16; o; o >>= 1) v = fminf(v, __shfl_down_sync(0xffffffffu, v, o));
    __syncthreads();
    if (lane == 0) sh[w] = v;
    __syncthreads();
    if (w == 0) {
        v = (lane < 8) ? sh[lane] : F_INF;
        for (int o = 4; o; o >>= 1) v = fminf(v, __shfl_down_sync(0xffffffffu, v, o));
    }
    return v;
}

__device__ __forceinline__ void atomicMaxF(float* addr, float v) {
    if (!(v == v)) return;
    int old = __float_as_int(*addr);
    while (__int_as_float(old) < v) {
        int assumed = old;
        old = atomicCAS((int*)addr, assumed, __float_as_int(v));
        if (old == assumed) break;
    }
}
__device__ __forceinline__ void atomicMinF(float* addr, float v) {
    if (!(v == v)) return;
    int old = __float_as_int(*addr);
    while (__int_as_float(old) > v) {
        int assumed = old;
        old = atomicCAS((int*)addr, assumed, __float_as_int(v));
        if (old == assumed) break;
    }
}

// ---------------- kernels ----------------

// Stage A: point clouds, masked loss sums, nan_cloud + global max
__global__ void k_pcd(const float* __restrict__ fake, const float* __restrict__ real) {
    int i = blockIdx.x * blockDim.x + threadIdx.x;  // exactly N_PTS threads
    int r = i / IMG_W, c = i % IMG_W;
    float dr = real[i], df = fake[i];
    bool vr = (dr > 0.f) && (dr < 65535.f);
    bool vf = (df > 0.f) && (df < 65535.f);
    float cf = (float)c, rf = (float)r;

    float zr = dr / 1000.f, zf = df / 1000.f;
    float xr = zr * (cf - CXc) / FXc, yr = zr * (rf - CYc) / FYc;
    float xf = zf * (cf - CXc) / FXc, yf = zf * (rf - CYc) / FYc;
    xr *= 1000.f; yr *= 1000.f; zr *= 1000.f;
    xf *= 1000.f; yf *= 1000.f; zf *= 1000.f;
    if (xr == 0.f) xr = 1e-7f;  if (yr == 0.f) yr = 1e-7f;  if (zr == 0.f) zr = 1e-7f;
    if (xf == 0.f) xf = 1e-7f;  if (yf == 0.f) yf = 1e-7f;  if (zf == 0.f) zf = 1e-7f;

    double dx = 0.0, dy = 0.0, dz = 0.0, dl = 0.0;
    int mm = 0;
    if (vr && vf) {
        float ex = xr - xf, ey = yr - yf, ez = zr - zf;
        dx = (double)(ex * ex); dy = (double)(ey * ey); dz = (double)(ez * ez);
        float d0 = logf(fabsf(zr)) - logf(fabsf(zf));
        dl = (double)(d0 * d0);
        mm = 1;
    }
    float4 nc = vf ? make_float4(xf, yf, zf, 0.f) : make_float4(0.f, 0.f, 0.f, 0.f);
    g_pts[i] = nc;
    float mxv = fmaxf(nc.x, fmaxf(nc.y, nc.z));

    double s;
    s = blockSumD(dx); if (threadIdx.x == 0) atomicAdd(&g_sX, s);
    s = blockSumD(dy); if (threadIdx.x == 0) atomicAdd(&g_sY, s);
    s = blockSumD(dz); if (threadIdx.x == 0) atomicAdd(&g_sZ, s);
    s = blockSumD(dl); if (threadIdx.x == 0) atomicAdd(&g_sL, s);
    int cs = blockSumI(mm); if (threadIdx.x == 0) atomicAdd(&g_cnt, cs);
    float bm = blockMaxF(mxv); if (threadIdx.x == 0) atomicMaxF(&g_max, bm);
}

// Stage B: 1000 RANSAC planes, JAX-exact threefry randint, prefetched point loads
__global__ void k_planes() {
    int j = blockIdx.x * blockDim.x + threadIdx.x;
    if (j >= N_PLANES) return;
    float m = g_max;

    unsigned idxs[3];
#pragma unroll
    for (int k = 0; k < 3; k++) {
        unsigned f = (unsigned)(j * 3 + k);
        unsigned o0, o1;
        threefry2x32(0u, 42u, f, 3000u + f, o0, o1);
        // span = 230400 > 2^16 => JAX multiplier wraps to 0 => idx = lower_bits % span
        idxs[k] = o1 % (unsigned)N_PTS;
    }
    // independent loads -> MLP=3
    float4 q0 = g_pts[idxs[0]];
    float4 q1 = g_pts[idxs[1]];
    float4 q2 = g_pts[idxs[2]];
    float3 p0 = make_float3(q0.x / m, q0.y / m, q0.z / m);
    float3 p1 = make_float3(q1.x / m, q1.y / m, q1.z / m);
    float3 p2 = make_float3(q2.x / m, q2.y / m, q2.z / m);

    float ax = p1.x - p0.x, ay = p1.y - p0.y, az = p1.z - p0.z;
    float bx = p2.x - p0.x, by = p2.y - p0.y, bz = p2.z - p0.z;
    float nx = ay * bz - az * by;
    float ny = az * bx - ax * bz;
    float nz = ax * by - ay * bx;
    float nn = sqrtf(nx * nx + ny * ny + nz * nz);
    nx /= nn; ny /= nn; nz /= nn;
    float kk = -(nx * p1.x + ny * p1.y + nz * p1.z);
    g_plane[j] = make_float4(nx, ny, nz, kk);
}

// Stage C: inlier counts. 256-pt tile (128 packed pairs), 4 planes/thread,
// FFMA2 packed math, 900 blocks for occupancy. Last block: argmax + rotation
// + self-clean of g_counts / ticket.
#define CT 256
#define CP (CT / 2)               // 128 pairs
#define CB (N_PTS / CT)           // 900, exact
__global__ void __launch_bounds__(256, 5) k_counts(const int* __restrict__ ep) {
    __shared__ unsigned long long sx[CP], sy[CP], sz[CP];
    __shared__ int s_last;
    __shared__ int sv[256], si[256];

    float th = get_thresh(*ep);
    float m = g_max;
    int t = threadIdx.x;

    // planes (broadcast into both packed halves)
    unsigned long long A[4], B4[4], C4[4], K4[4];
    int cnt[4] = {0, 0, 0, 0};
#pragma unroll
    for (int p = 0; p < 4; p++) {
        int j = t + p * 256;
        float4 pl = g_plane[j < N_PLANES ? j : 0];
        A[p]  = pack2(pl.x, pl.x);
        B4[p] = pack2(pl.y, pl.y);
        C4[p] = pack2(pl.z, pl.z);
        K4[p] = pack2(pl.w, pl.w);
    }

    // tile load: point pairs, normalized exactly like reference (f32 divide)
    int base = blockIdx.x * CT;
    if (t < CP) {
        float4 q0 = g_pts[base + 2 * t];
        float4 q1 = g_pts[base + 2 * t + 1];
        sx[t] = pack2(q0.x / m, q1.x / m);
        sy[t] = pack2(q0.y / m, q1.y / m);
        sz[t] = pack2(q0.z / m, q1.z / m);
    }
    __syncthreads();

#pragma unroll 8
    for (int i = 0; i < CP; i++) {
        unsigned long long x2 = sx[i], y2 = sy[i], z2 = sz[i];
#pragma unroll
        for (int p = 0; p < 4; p++) {
            unsigned long long d2 = fma2(x2, A[p], fma2(y2, B4[p], fma2(z2, C4[p], K4[p])));
            float d0, d1; unpack2(d2, d0, d1);
            cnt[p] += (fabsf(d0) <= th);
            cnt[p] += (fabsf(d1) <= th);
        }
    }
#pragma unroll
    for (int p = 0; p < 4; p++) {
        int j = t + p * 256;
        if (j < N_PLANES) atomicAdd(&g_counts[j], cnt[p]);
    }

    // ---- last-block tail: argmax (first max) + best-plane rotation ----
    __threadfence();
    if (t == 0) {
        int old = atomicAdd(&g_tick_counts, 1);
        s_last = (old == (int)gridDim.x - 1);
    }
    __syncthreads();
    if (!s_last) return;

    int bv = -2, bi = 0;
    for (int j = t; j < N_PLANES; j += 256) {
        int cc = __ldcg(&g_counts[j]);
        int v = (cc > MIN_PTS) ? cc : -1;
        if (v > bv) { bv = v; bi = j; }   // ascending j => first max kept
    }
    sv[t] = bv; si[t] = bi;
    __syncthreads();
    for (int s = 128; s > 0; s >>= 1) {
        if (t < s) {
            if (sv[t + s] > sv[t] || (sv[t + s] == sv[t] && si[t + s] < si[t])) {
                sv[t] = sv[t + s]; si[t] = si[t + s];
            }
        }
        __syncthreads();
    }
    if (t == 0) {
        int best = si[0];
        float4 pl = g_plane[best];
        float a = pl.x, b = pl.y, c = pl.z, d = pl.w;
        float n2 = a * a + b * b + c * c;
        float cos_t = c / sqrtf(n2);
        float sin_t = sqrtf((a * a + b * b) / n2);
        float sab = sqrtf(a * a + b * b);
        float u1 = b / sab, u2 = -a / sab;
        g_bp[0] = a; g_bp[1] = b; g_bp[2] = c; g_bp[3] = d;
        g_bp[4] = -u2 * sin_t;   // R[2,0]
        g_bp[5] =  u1 * sin_t;   // R[2,1]
        g_bp[6] =  cos_t;        // R[2,2]
        g_bp[7] =  d / c;        // trans z
        g_tick_counts = 0;       // self-clean ticket
    }
    // self-clean counts for next call
    for (int j = t; j < N_PLANES; j += 256) g_counts[j] = 0;
}

// Stage D: single pass: inlier stats; last block finalizes output and
// self-cleans ALL scalar accumulators.
// Uses identity: sum|zc-zmax| = icnt*zmax - S, sum|zc-zmin| = S - icnt*zmin.
__global__ void k_zc(const int* __restrict__ ep, float* __restrict__ out, int n) {
    __shared__ int s_last;
    float th = get_thresh(*ep);
    float m = g_max;
    int i = blockIdx.x * blockDim.x + threadIdx.x;
    float4 q = g_pts[i];
    float x = q.x / m, y = q.y / m, z = q.z / m;
    float dist = fmaf(x, g_bp[0], fmaf(y, g_bp[1], fmaf(z, g_bp[2], g_bp[3])));
    bool inl = fabsf(dist) <= th;
    float zc = x * g_bp[4] + y * g_bp[5] + (z + g_bp[7]) * g_bp[6];

    int    ic  = blockSumI(inl ? 1 : 0);
    float  zmx = blockMaxF(inl ? zc : -F_INF);
    float  zmn = blockMinF(inl ? zc :  F_INF);
    double s   = blockSumD(inl ? (double)zc : 0.0);
    if (threadIdx.x == 0) {
        atomicAdd(&g_icnt, ic);
        atomicMaxF(&g_zmax, zmx);
        atomicMinF(&g_zmin, zmn);
        atomicAdd(&g_sZC, s);
    }

    __threadfence();
    if (threadIdx.x == 0) {
        int old = atomicAdd(&g_tick_zc, 1);
        s_last = (old == (int)gridDim.x - 1);
    }
    __syncthreads();
    if (!(s_last && threadIdx.x == 0)) return;

    // ---- finalize ----
    float cntf = (float)(g_cnt > 1 ? g_cnt : 1);
    float lX = sqrtf((float)g_sX / cntf);
    float lY = sqrtf((float)g_sY / cntf);
    float lZ = sqrtf((float)g_sZ / cntf);
    float rl = 10000.f * sqrtf((float)g_sL / cntf);
    float l17 = rl * fabsf(10.f * (3.f - expf(lX) - expf(lY) - expf(lZ)));

    int icr = g_icnt;
    float below, above;
    if (icr <= 0) {
        below = 0.f; above = 0.f;
    } else {
        float meanz = (float)(g_sZC / (double)icr);
        below = g_zmax - meanz;
        above = meanz - g_zmin;
    }
    if (above == 0.f) above = 1e-7f;
    float pmd = 1000.f * (above + below);
    float curv = l17 + pmd;
    float vals[7] = { rl, lX, lY, lZ, pmd, l17, curv };
    for (int k = 0; k < n; k++) out[k] = (k < 7) ? vals[k] : 0.f;

    // ---- self-clean for next call ----
    g_sX = 0.0; g_sY = 0.0; g_sZ = 0.0; g_sL = 0.0;
    g_cnt = 0;  g_icnt = 0;
    g_max  = NEG_FLT_MAX;
    g_zmax = NEG_FLT_MAX;
    g_zmin = POS_FLT_MAX;
    g_sZC  = 0.0;
    g_tick_zc = 0;
}

// ---------------- launch ----------------
extern "C" void kernel_launch(void* const* d_in, const int* in_sizes, int n_in,
                              void* d_out, int out_size) {
    const float* fake = (const float*)d_in[0];
    const float* real = (const float*)d_in[1];
    const int*   ep   = (const int*)d_in[2];
    float* out = (float*)d_out;

    const int NB = N_PTS / 256;  // 900, exact

    k_pcd<<<NB, 256>>>(fake, real);
    k_planes<<<8, 128>>>();
    k_counts<<<CB, 256>>>(ep);
    k_zc<<<NB, 256>>>(ep, out, out_size);
}